// round 2
// baseline (speedup 1.0000x reference)
#include <cuda_runtime.h>
#include <cuda_bf16.h>

// Problem constants
#define SIGMA   16
#define P       33
#define Hh      256
#define Wn      256
#define Bn      4
#define Kn      64
#define Nn      (Bn * Kn)          // 256 keypoints per side
#define NPATCH  (2 * Nn * Bn)      // 2048 total patches (2 sides)
#define C1      32                  // conv1 out channels
#define O1      31                  // conv1 output spatial (33-3+1)
#define C2      64                  // conv2 out channels
#define O2      15                  // conv2 output spatial ((31-3)/2+1)
#define OUTF    128                 // linear output size
#define H1SZ    (C1 * O1 * O1)      // 30752 floats per patch

// Scratch: conv1 activations for all patches (~252 MB) + features (~1 MB)
__device__ float g_h1[(size_t)NPATCH * H1SZ];
__device__ float g_feat[(size_t)NPATCH * OUTF];

// ---------------------------------------------------------------------------
// Kernel 1: crop (fused, via keypoint indexing) + conv1 3->32 3x3 VALID + ReLU
// One block per patch. Patch + w1 staged in smem.
// ---------------------------------------------------------------------------
__global__ __launch_bounds__(512) void conv1_kernel(
    const float* __restrict__ img_g, const float* __restrict__ img_s,
    const float* __restrict__ kp_g,  const float* __restrict__ kp_s,
    const float* __restrict__ w1,    const float* __restrict__ b1)
{
    const int p    = blockIdx.x;          // 0..2047
    const int side = p >> 10;             // 0 = ground, 1 = satellite
    const int r    = p & 1023;
    const int n    = r >> 2;              // keypoint index 0..255
    const int b    = r & 3;               // image batch index 0..3

    const float* kps = side ? kp_s : kp_g;
    const float* img = side ? img_s : img_g;

    const float kx = kps[n * 2 + 0] * 256.0f;
    const float ky = kps[n * 2 + 1] * 256.0f;
    int sx = (int)floorf(kx) - SIGMA;
    int sy = (int)floorf(ky) - SIGMA;
    sx = min(max(sx, 0), Wn - P);
    sy = min(max(sy, 0), Hh - P);

    __shared__ float patch[3 * P * P];    // 3267 floats
    __shared__ float sw1[C1 * 27];        // 864 floats
    __shared__ float sb1[C1];

    for (int t = threadIdx.x; t < 3 * P * P; t += blockDim.x) {
        int c   = t / (P * P);
        int rem = t - c * (P * P);
        int y   = rem / P;
        int x   = rem - y * P;
        patch[t] = img[(((size_t)b * 3 + c) * Hh + (sy + y)) * Wn + (sx + x)];
    }
    for (int t = threadIdx.x; t < C1 * 27; t += blockDim.x) sw1[t] = w1[t];
    if (threadIdx.x < C1) sb1[threadIdx.x] = b1[threadIdx.x];
    __syncthreads();

    float* out = g_h1 + (size_t)p * H1SZ;
    for (int t = threadIdx.x; t < H1SZ; t += blockDim.x) {
        int oc  = t / (O1 * O1);
        int rem = t - oc * (O1 * O1);
        int oy  = rem / O1;
        int ox  = rem - oy * O1;
        float s = sb1[oc];
        const float* w = sw1 + oc * 27;
        #pragma unroll
        for (int ic = 0; ic < 3; ic++) {
            const float* pp = patch + (ic * P + oy) * P + ox;
            #pragma unroll
            for (int kky = 0; kky < 3; kky++) {
                #pragma unroll
                for (int kkx = 0; kkx < 3; kkx++) {
                    s = fmaf(pp[kky * P + kkx], w[(ic * 3 + kky) * 3 + kkx], s);
                }
            }
        }
        out[t] = fmaxf(s, 0.0f);
    }
}

// ---------------------------------------------------------------------------
// Kernel 2: conv2 32->64 3x3 stride2 VALID + ReLU + GAP + linear 64->128
// One block per patch; h1 tile in 123 KB dynamic smem; 512 threads.
// ---------------------------------------------------------------------------
__global__ __launch_bounds__(512) void conv2_kernel(
    const float* __restrict__ w2, const float* __restrict__ b2,
    const float* __restrict__ wl, const float* __restrict__ bl)
{
    extern __shared__ float smem[];
    float* h1  = smem;            // H1SZ floats
    float* gap = smem + H1SZ;     // C2 floats

    const int p = blockIdx.x;
    const float* src = g_h1 + (size_t)p * H1SZ;
    for (int t = threadIdx.x; t < H1SZ; t += blockDim.x) h1[t] = src[t];
    if (threadIdx.x < C2) gap[threadIdx.x] = 0.0f;
    __syncthreads();

    // 64 * 225 = 14400 conv2 outputs, accumulate ReLU'd values into gap[oc]
    for (int t = threadIdx.x; t < C2 * O2 * O2; t += blockDim.x) {
        int oc  = t / (O2 * O2);
        int pos = t - oc * (O2 * O2);
        int oy  = pos / O2;
        int ox  = pos - oy * O2;
        float s = __ldg(&b2[oc]);
        const float* wbase = w2 + (size_t)oc * C1 * 9;
        const float* hbase = h1 + (2 * oy) * O1 + 2 * ox;
        #pragma unroll 4
        for (int ic = 0; ic < C1; ic++) {
            const float* hp = hbase + ic * (O1 * O1);
            const float* wp = wbase + ic * 9;
            float w0 = __ldg(&wp[0]), w1v = __ldg(&wp[1]), w2v = __ldg(&wp[2]);
            float w3 = __ldg(&wp[3]), w4  = __ldg(&wp[4]), w5  = __ldg(&wp[5]);
            float w6 = __ldg(&wp[6]), w7  = __ldg(&wp[7]), w8  = __ldg(&wp[8]);
            s = fmaf(hp[0],          w0,  s);
            s = fmaf(hp[1],          w1v, s);
            s = fmaf(hp[2],          w2v, s);
            s = fmaf(hp[O1 + 0],     w3,  s);
            s = fmaf(hp[O1 + 1],     w4,  s);
            s = fmaf(hp[O1 + 2],     w5,  s);
            s = fmaf(hp[2 * O1 + 0], w6,  s);
            s = fmaf(hp[2 * O1 + 1], w7,  s);
            s = fmaf(hp[2 * O1 + 2], w8,  s);
        }
        s = fmaxf(s, 0.0f);
        atomicAdd(&gap[oc], s);
    }
    __syncthreads();

    // linear: f[o] = bl[o] + sum_c (gap[c]/225) * wl[o*64+c]
    const float inv = 1.0f / (float)(O2 * O2);
    for (int o = threadIdx.x; o < OUTF; o += blockDim.x) {
        float f = __ldg(&bl[o]);
        const float* wrow = wl + o * C2;
        #pragma unroll
        for (int c = 0; c < C2; c++) {
            f = fmaf(gap[c] * inv, __ldg(&wrow[c]), f);
        }
        g_feat[(size_t)p * OUTF + o] = f;
    }
}

// ---------------------------------------------------------------------------
// Kernel 3: loss = mean((fg - fs)^2) over 1024*128 paired elements
// Single block reduction.
// ---------------------------------------------------------------------------
__global__ __launch_bounds__(1024) void loss_kernel(float* __restrict__ out)
{
    const int TOTAL = Nn * Bn * OUTF;     // 131072 pairs
    float s = 0.0f;
    for (int i = threadIdx.x; i < TOTAL; i += blockDim.x) {
        float d = g_feat[i] - g_feat[i + TOTAL];
        s = fmaf(d, d, s);
    }
    // block reduce
    __shared__ float red[32];
    #pragma unroll
    for (int off = 16; off > 0; off >>= 1)
        s += __shfl_down_sync(0xFFFFFFFF, s, off);
    int wid = threadIdx.x >> 5;
    int lid = threadIdx.x & 31;
    if (lid == 0) red[wid] = s;
    __syncthreads();
    if (wid == 0) {
        s = (lid < (int)(blockDim.x >> 5)) ? red[lid] : 0.0f;
        #pragma unroll
        for (int off = 16; off > 0; off >>= 1)
            s += __shfl_down_sync(0xFFFFFFFF, s, off);
        if (lid == 0) out[0] = s / (float)TOTAL;
    }
}

extern "C" void kernel_launch(void* const* d_in, const int* in_sizes, int n_in,
                              void* d_out, int out_size)
{
    const float* img_g = (const float*)d_in[0];
    const float* img_s = (const float*)d_in[1];
    const float* kp_g  = (const float*)d_in[2];
    const float* kp_s  = (const float*)d_in[3];
    const float* w1    = (const float*)d_in[4];
    const float* b1    = (const float*)d_in[5];
    const float* w2    = (const float*)d_in[6];
    const float* b2    = (const float*)d_in[7];
    const float* wl    = (const float*)d_in[8];
    const float* bl    = (const float*)d_in[9];
    float* out = (float*)d_out;

    static bool attr_set = false;
    const int smem2 = (H1SZ + C2) * (int)sizeof(float);   // 123264 B
    if (!attr_set) {
        cudaFuncSetAttribute(conv2_kernel,
                             cudaFuncAttributeMaxDynamicSharedMemorySize, smem2);
        attr_set = true;
    }

    conv1_kernel<<<NPATCH, 512>>>(img_g, img_s, kp_g, kp_s, w1, b1);
    conv2_kernel<<<NPATCH, 512, smem2>>>(w2, b2, wl, bl);
    loss_kernel<<<1, 1024>>>(out);
}

// round 3
// speedup vs baseline: 5.8877x; 5.8877x over previous
#include <cuda_runtime.h>
#include <cuda_bf16.h>

// Problem constants
#define SIGMA   16
#define P       33
#define Hh      256
#define Wn      256
#define Bn      4
#define Kn      64
#define Nn      (Bn * Kn)          // 256 keypoints per side
#define NPATCH  (2 * Nn * Bn)      // 2048 total patches
#define C1      32
#define O1      31                 // conv1 out spatial
#define C2      64
#define O2      15                 // conv2 out spatial
#define OUTF    128
#define H1SZ    (C1 * O1 * O1)     // 30752

// smem layout (floats)
#define OFF_PATCH 0                       // 3*33*33 = 3267
#define OFF_W1    (OFF_PATCH + 3*P*P)     // 864
#define OFF_B1    (OFF_W1 + C1*27)        // 32
#define OFF_W2    (OFF_B1 + C1)           // 64*32*9 = 18432
#define OFF_B2    (OFF_W2 + C2*C1*9)      // 64
#define OFF_H1    (OFF_B2 + C2)           // 30752
#define OFF_GAP   (OFF_H1 + H1SZ)         // 64
#define SMEM_FLOATS (OFF_GAP + C2)        // 53475
#define SMEM_BYTES (SMEM_FLOATS * 4)      // 213900 B

__device__ float g_feat[(size_t)NPATCH * OUTF];

// ---------------------------------------------------------------------------
// Fused: crop + conv1 + conv2 + GAP + linear. One block per patch.
// ---------------------------------------------------------------------------
__global__ __launch_bounds__(512) void fused_kernel(
    const float* __restrict__ img_g, const float* __restrict__ img_s,
    const float* __restrict__ kp_g,  const float* __restrict__ kp_s,
    const float* __restrict__ w1,    const float* __restrict__ b1,
    const float* __restrict__ w2,    const float* __restrict__ b2,
    const float* __restrict__ wl,    const float* __restrict__ bl)
{
    extern __shared__ float sm[];
    float* patch = sm + OFF_PATCH;
    float* sw1   = sm + OFF_W1;
    float* sb1   = sm + OFF_B1;
    float* sw2   = sm + OFF_W2;
    float* sb2   = sm + OFF_B2;
    float* h1    = sm + OFF_H1;
    float* gap   = sm + OFF_GAP;

    const int tid  = threadIdx.x;
    const int p    = blockIdx.x;
    const int side = p >> 10;
    const int r    = p & 1023;
    const int n    = r >> 2;
    const int b    = r & 3;

    const float* kps = side ? kp_s : kp_g;
    const float* img = side ? img_s : img_g;

    const float kx = kps[n * 2 + 0] * 256.0f;
    const float ky = kps[n * 2 + 1] * 256.0f;
    int sx = (int)floorf(kx) - SIGMA;
    int sy = (int)floorf(ky) - SIGMA;
    sx = min(max(sx, 0), Wn - P);
    sy = min(max(sy, 0), Hh - P);

    // ---- stage patch + all weights ----
    for (int t = tid; t < 3 * P * P; t += 512) {
        int c   = t / (P * P);
        int rem = t - c * (P * P);
        int y   = rem / P;
        int x   = rem - y * P;
        patch[t] = img[(((size_t)b * 3 + c) * Hh + (sy + y)) * Wn + (sx + x)];
    }
    for (int t = tid; t < C1 * 27; t += 512) sw1[t] = w1[t];
    for (int t = tid; t < C2 * C1 * 9; t += 512) sw2[t] = w2[t];
    if (tid < C1) sb1[tid] = b1[tid];
    if (tid < C2) sb2[tid] = b2[tid];
    if (tid < C2) gap[tid] = 0.0f;
    __syncthreads();

    // ---- conv1: strips (oc-pair, oy); 496 threads active ----
    if (tid < 16 * O1) {
        const int oy  = tid % O1;
        const int ocp = tid / O1;        // 0..15 -> oc = 2*ocp, 2*ocp+1
        float acc0[O1], acc1[O1];
        const float bb0 = sb1[2 * ocp], bb1 = sb1[2 * ocp + 1];
        #pragma unroll
        for (int x = 0; x < O1; x++) { acc0[x] = bb0; acc1[x] = bb1; }

        #pragma unroll
        for (int ic = 0; ic < 3; ic++) {
            #pragma unroll
            for (int kyy = 0; kyy < 3; kyy++) {
                const float* row = patch + (ic * P + oy + kyy) * P;
                const float* wp0 = sw1 + (2 * ocp)     * 27 + ic * 9 + kyy * 3;
                const float* wp1 = sw1 + (2 * ocp + 1) * 27 + ic * 9 + kyy * 3;
                float a0 = wp0[0], a1 = wp0[1], a2 = wp0[2];
                float c0 = wp1[0], c1 = wp1[1], c2 = wp1[2];
                #pragma unroll
                for (int x = 0; x < P; x++) {
                    float v = row[x];
                    if (x <= 30) { acc0[x]   = fmaf(v, a0, acc0[x]);   acc1[x]   = fmaf(v, c0, acc1[x]); }
                    if (x >= 1 && x <= 31) { acc0[x-1] = fmaf(v, a1, acc0[x-1]); acc1[x-1] = fmaf(v, c1, acc1[x-1]); }
                    if (x >= 2) { acc0[x-2] = fmaf(v, a2, acc0[x-2]); acc1[x-2] = fmaf(v, c2, acc1[x-2]); }
                }
            }
        }
        float* o0 = h1 + ((2 * ocp)     * O1 + oy) * O1;
        float* o1 = h1 + ((2 * ocp + 1) * O1 + oy) * O1;
        #pragma unroll
        for (int x = 0; x < O1; x++) {
            o0[x] = fmaxf(acc0[x], 0.0f);
            o1[x] = fmaxf(acc1[x], 0.0f);
        }
    }
    __syncthreads();

    // ---- conv2 + relu + partial GAP: strips (oc-quad, oy); 240 threads ----
    if (tid < 16 * O2) {
        const int oy  = tid % O2;
        const int ocq = tid / O2;        // 0..15 -> oc = 4*ocq..4*ocq+3
        float acc[4][O2];
        #pragma unroll
        for (int j = 0; j < 4; j++) {
            float bb = sb2[4 * ocq + j];
            #pragma unroll
            for (int x = 0; x < O2; x++) acc[j][x] = bb;
        }

        for (int ic = 0; ic < C1; ic++) {
            #pragma unroll
            for (int kyy = 0; kyy < 3; kyy++) {
                const float* row = h1 + (ic * O1 + 2 * oy + kyy) * O1;
                float w[4][3];
                #pragma unroll
                for (int j = 0; j < 4; j++) {
                    const float* wp = sw2 + ((4 * ocq + j) * C1 + ic) * 9 + kyy * 3;
                    w[j][0] = wp[0]; w[j][1] = wp[1]; w[j][2] = wp[2];
                }
                #pragma unroll
                for (int x = 0; x < O1; x++) {
                    float v = row[x];
                    if ((x & 1) == 0) {
                        if (x <= 28) {
                            const int o = x >> 1;
                            #pragma unroll
                            for (int j = 0; j < 4; j++) acc[j][o] = fmaf(v, w[j][0], acc[j][o]);
                        }
                        if (x >= 2) {
                            const int o = (x >> 1) - 1;
                            #pragma unroll
                            for (int j = 0; j < 4; j++) acc[j][o] = fmaf(v, w[j][2], acc[j][o]);
                        }
                    } else {
                        const int o = x >> 1;
                        #pragma unroll
                        for (int j = 0; j < 4; j++) acc[j][o] = fmaf(v, w[j][1], acc[j][o]);
                    }
                }
            }
        }
        // relu + per-thread GAP partials -> smem atomics
        #pragma unroll
        for (int j = 0; j < 4; j++) {
            float s = 0.0f;
            #pragma unroll
            for (int x = 0; x < O2; x++) s += fmaxf(acc[j][x], 0.0f);
            atomicAdd(&gap[4 * ocq + j], s);
        }
    }
    __syncthreads();

    // ---- linear 64 -> 128 ----
    const float inv = 1.0f / (float)(O2 * O2);
    if (tid < OUTF) {
        float f = __ldg(&bl[tid]);
        const float* wrow = wl + tid * C2;
        #pragma unroll
        for (int c = 0; c < C2; c++) f = fmaf(gap[c] * inv, __ldg(&wrow[c]), f);
        g_feat[(size_t)p * OUTF + tid] = f;
    }
}

// ---------------------------------------------------------------------------
// loss = mean((fg - fs)^2), single-block deterministic reduction
// ---------------------------------------------------------------------------
__global__ __launch_bounds__(1024) void loss_kernel(float* __restrict__ out)
{
    const int TOTAL = Nn * Bn * OUTF;     // 131072
    float s = 0.0f;
    for (int i = threadIdx.x; i < TOTAL; i += blockDim.x) {
        float d = g_feat[i] - g_feat[i + TOTAL];
        s = fmaf(d, d, s);
    }
    __shared__ float red[32];
    #pragma unroll
    for (int off = 16; off > 0; off >>= 1)
        s += __shfl_down_sync(0xFFFFFFFF, s, off);
    int wid = threadIdx.x >> 5;
    int lid = threadIdx.x & 31;
    if (lid == 0) red[wid] = s;
    __syncthreads();
    if (wid == 0) {
        s = (lid < 32) ? red[lid] : 0.0f;
        #pragma unroll
        for (int off = 16; off > 0; off >>= 1)
            s += __shfl_down_sync(0xFFFFFFFF, s, off);
        if (lid == 0) out[0] = s / (float)TOTAL;
    }
}

extern "C" void kernel_launch(void* const* d_in, const int* in_sizes, int n_in,
                              void* d_out, int out_size)
{
    const float* img_g = (const float*)d_in[0];
    const float* img_s = (const float*)d_in[1];
    const float* kp_g  = (const float*)d_in[2];
    const float* kp_s  = (const float*)d_in[3];
    const float* w1    = (const float*)d_in[4];
    const float* b1    = (const float*)d_in[5];
    const float* w2    = (const float*)d_in[6];
    const float* b2    = (const float*)d_in[7];
    const float* wl    = (const float*)d_in[8];
    const float* bl    = (const float*)d_in[9];
    float* out = (float*)d_out;

    static bool attr_set = false;
    if (!attr_set) {
        cudaFuncSetAttribute(fused_kernel,
                             cudaFuncAttributeMaxDynamicSharedMemorySize, SMEM_BYTES);
        attr_set = true;
    }

    fused_kernel<<<NPATCH, 512, SMEM_BYTES>>>(img_g, img_s, kp_g, kp_s,
                                              w1, b1, w2, b2, wl, bl);
    loss_kernel<<<1, 1024>>>(out);
}